// round 4
// baseline (speedup 1.0000x reference)
#include <cuda_runtime.h>
#include <cuda_bf16.h>
#include <cstdint>
#include <cstddef>
#include <math.h>

#define DEVI static __device__ __forceinline__

// Problem dims
constexpr int cT = 256, cN = 512, cD = 512, cH = 512, cO = 512;
constexpr size_t TN = (size_t)cT * cN;                    // 131072 rows
constexpr size_t QKV_E = (size_t)cN * cT * cH;            // 67108864 elems
constexpr size_t P_E = (size_t)cN * cT * cT;              // 33554432 elems

// ---------------------------------------------------------------------------
// Device-global scratch (allocation-free rule)
// ---------------------------------------------------------------------------
__device__ __nv_bfloat16 gAhi[TN * cD];
__device__ __nv_bfloat16 gAlo[TN * cD];
__device__ __nv_bfloat16 gWthi[3 * 512 * 512];
__device__ __nv_bfloat16 gWtlo[3 * 512 * 512];
__device__ __nv_bfloat16 gQhi[QKV_E], gQlo[QKV_E];   // [n][t][h]
__device__ __nv_bfloat16 gKhi[QKV_E], gKlo[QKV_E];   // [n][s][h]
__device__ __nv_bfloat16 gVhi[QKV_E], gVlo[QKV_E];   // [n][s][o]
__device__ __nv_bfloat16 gVthi[QKV_E], gVtlo[QKV_E]; // [n][o][s]
__device__ __nv_bfloat16 gPhi[P_E], gPlo[P_E];       // [n][t][s]

// ---------------------------------------------------------------------------
// Small helpers
// ---------------------------------------------------------------------------
DEVI uint32_t smem_u32(const void* p) {
    uint32_t a;
    asm("{ .reg .u64 t; cvta.to.shared.u64 t, %1; cvt.u32.u64 %0, t; }"
        : "=r"(a) : "l"(p));
    return a;
}
DEVI void cp16(uint32_t dst, const void* src) {
    asm volatile("cp.async.cg.shared.global [%0], [%1], 16;"
                 :: "r"(dst), "l"(src) : "memory");
}
DEVI void cp_commit() { asm volatile("cp.async.commit_group;" ::: "memory"); }
DEVI void cp_wait1()  { asm volatile("cp.async.wait_group 1;" ::: "memory"); }
DEVI uint32_t lds32(uint32_t a) {
    uint32_t v;
    asm volatile("ld.shared.b32 %0, [%1];" : "=r"(v) : "r"(a));
    return v;
}
DEVI void mma16816(float* c, const uint32_t* a, const uint32_t* b) {
    asm volatile(
        "mma.sync.aligned.m16n8k16.row.col.f32.bf16.bf16.f32 "
        "{%0,%1,%2,%3}, {%4,%5,%6,%7}, {%8,%9}, {%0,%1,%2,%3};"
        : "+f"(c[0]), "+f"(c[1]), "+f"(c[2]), "+f"(c[3])
        : "r"(a[0]), "r"(a[1]), "r"(a[2]), "r"(a[3]), "r"(b[0]), "r"(b[1]));
}
DEVI uint32_t pack2(__nv_bfloat16 a, __nv_bfloat16 b) {
    return (uint32_t)__bfloat16_as_ushort(a) |
           ((uint32_t)__bfloat16_as_ushort(b) << 16);
}
// split fp32 pair -> bf16 hi pair + bf16 lo pair, store as 32-bit each
DEVI void split_store_pair(__nv_bfloat16* hi, __nv_bfloat16* lo, size_t off,
                           float v0, float v1) {
    __nv_bfloat16 h0 = __float2bfloat16(v0);
    __nv_bfloat16 h1 = __float2bfloat16(v1);
    __nv_bfloat16 l0 = __float2bfloat16(v0 - __bfloat162float(h0));
    __nv_bfloat16 l1 = __float2bfloat16(v1 - __bfloat162float(h1));
    *reinterpret_cast<uint32_t*>(hi + off) = pack2(h0, h1);
    *reinterpret_cast<uint32_t*>(lo + off) = pack2(l0, l1);
}

// ---------------------------------------------------------------------------
// Shared GEMM core.
// A tiles: [BM rows][16 k] bf16, k-contiguous, 32B/row.  hi region then lo.
// B tiles: [BN rows(n)][16 k] bf16, k-contiguous.        hi region then lo.
// Per-warp tile fixed 32(M) x 64(N): MT=2 m16-tiles, NT=8 n8-tiles.
// Split-3: acc += Ahi*Bhi + Ahi*Blo + Alo*Bhi  (fp32)
// ---------------------------------------------------------------------------
template <int BM, int BN>
DEVI void gemm_main(const __nv_bfloat16* Ahi, const __nv_bfloat16* Alo, size_t lda,
                    const __nv_bfloat16* Bhi, const __nv_bfloat16* Blo, size_t ldb,
                    int K, char* smemRaw, float acc[2][8][4]) {
    constexpr int WC = BN / 64;                 // warp cols
    constexpr uint32_t AB = (uint32_t)BM * 32;  // bytes per A half-region
    constexpr uint32_t BB = (uint32_t)BN * 32;
    constexpr uint32_t STAGE = 2 * AB + 2 * BB;

    const uint32_t sb = smem_u32(smemRaw);
    const int tid = threadIdx.x;
    const int wid = tid >> 5, lane = tid & 31;
    const int wr = wid / WC, wc = wid % WC;
    const int gid = lane >> 2, t4 = lane & 3;

#pragma unroll
    for (int mt = 0; mt < 2; mt++)
#pragma unroll
        for (int nt = 0; nt < 8; nt++)
#pragma unroll
            for (int j = 0; j < 4; j++) acc[mt][nt][j] = 0.f;

    auto load_stage = [&](int k0, uint32_t base) {
        // A region (hi rows then lo rows), 2 x 16B chunks per row
        {
            const int total = BM * 4;
            for (int i = tid; i < total; i += 256) {
                int half = (i >= BM * 2);
                int j = half ? i - BM * 2 : i;
                int r = j >> 1, c = j & 1;
                const __nv_bfloat16* s =
                    (half ? Alo : Ahi) + (size_t)r * lda + k0 + c * 8;
                cp16(base + (half ? AB : 0u) + (uint32_t)(r * 32 + c * 16), s);
            }
        }
        // B region
        {
            const int total = BN * 4;
            for (int i = tid; i < total; i += 256) {
                int half = (i >= BN * 2);
                int j = half ? i - BN * 2 : i;
                int r = j >> 1, c = j & 1;
                const __nv_bfloat16* s =
                    (half ? Blo : Bhi) + (size_t)r * ldb + k0 + c * 8;
                cp16(base + 2 * AB + (half ? BB : 0u) +
                         (uint32_t)(r * 32 + c * 16), s);
            }
        }
        cp_commit();
    };

    const int NK = K / 16;
    load_stage(0, sb);
    for (int kt = 0; kt < NK; kt++) {
        const int cur = kt & 1;
        if (kt + 1 < NK) load_stage((kt + 1) * 16, sb + (uint32_t)(cur ^ 1) * STAGE);
        else cp_commit();  // empty group keeps the count consistent
        cp_wait1();
        __syncthreads();

        const uint32_t aBase = sb + (uint32_t)cur * STAGE;
        const uint32_t bBase = aBase + 2 * AB;

        uint32_t aH[2][4], aL[2][4], bH[8][2], bL[8][2];
#pragma unroll
        for (int mt = 0; mt < 2; mt++) {
            uint32_t r0 = aBase + (uint32_t)((wr * 32 + mt * 16 + gid) * 32 + t4 * 4);
            uint32_t r1 = r0 + 8 * 32;
            aH[mt][0] = lds32(r0);       aH[mt][1] = lds32(r1);
            aH[mt][2] = lds32(r0 + 16);  aH[mt][3] = lds32(r1 + 16);
            aL[mt][0] = lds32(r0 + AB);      aL[mt][1] = lds32(r1 + AB);
            aL[mt][2] = lds32(r0 + AB + 16); aL[mt][3] = lds32(r1 + AB + 16);
        }
#pragma unroll
        for (int nt = 0; nt < 8; nt++) {
            uint32_t r = bBase + (uint32_t)((wc * 64 + nt * 8 + gid) * 32 + t4 * 4);
            bH[nt][0] = lds32(r);       bH[nt][1] = lds32(r + 16);
            bL[nt][0] = lds32(r + BB);  bL[nt][1] = lds32(r + BB + 16);
        }
#pragma unroll
        for (int mt = 0; mt < 2; mt++)
#pragma unroll
            for (int nt = 0; nt < 8; nt++) {
                mma16816(acc[mt][nt], aH[mt], bH[nt]);
                mma16816(acc[mt][nt], aH[mt], bL[nt]);
                mma16816(acc[mt][nt], aL[mt], bH[nt]);
            }
        __syncthreads();
    }
}

// ---------------------------------------------------------------------------
// Kernel 1: split inputs fp32 -> bf16 hi/lo
// ---------------------------------------------------------------------------
__global__ void __launch_bounds__(256) k_split_in(const float* __restrict__ in) {
    size_t i = (size_t)blockIdx.x * 256 + threadIdx.x;  // one float4 each
    const float4 v = reinterpret_cast<const float4*>(in)[i];
    __nv_bfloat16 h0 = __float2bfloat16(v.x), h1 = __float2bfloat16(v.y);
    __nv_bfloat16 h2 = __float2bfloat16(v.z), h3 = __float2bfloat16(v.w);
    __nv_bfloat16 l0 = __float2bfloat16(v.x - __bfloat162float(h0));
    __nv_bfloat16 l1 = __float2bfloat16(v.y - __bfloat162float(h1));
    __nv_bfloat16 l2 = __float2bfloat16(v.z - __bfloat162float(h2));
    __nv_bfloat16 l3 = __float2bfloat16(v.w - __bfloat162float(h3));
    uint2 ph = make_uint2(pack2(h0, h1), pack2(h2, h3));
    uint2 pl = make_uint2(pack2(l0, l1), pack2(l2, l3));
    reinterpret_cast<uint2*>(gAhi)[i] = ph;
    reinterpret_cast<uint2*>(gAlo)[i] = pl;
}

// ---------------------------------------------------------------------------
// Kernel 2: transpose + split weights: Wt[w][h][d] = W[w][d][h]
// ---------------------------------------------------------------------------
__global__ void __launch_bounds__(256) k_split_w(const float* __restrict__ Wq,
                                                 const float* __restrict__ Wk,
                                                 const float* __restrict__ Wv) {
    __shared__ float tile[32][33];
    const int z = blockIdx.z;
    const float* W = (z == 0) ? Wq : (z == 1) ? Wk : Wv;
    const int d0 = blockIdx.x * 32, h0 = blockIdx.y * 32;
    const int tx = threadIdx.x, ty = threadIdx.y;  // block (32, 8)
    for (int i = ty; i < 32; i += 8)
        tile[i][tx] = W[(size_t)(d0 + i) * 512 + h0 + tx];
    __syncthreads();
    for (int i = ty; i < 32; i += 8) {
        float v = tile[tx][i];
        __nv_bfloat16 h = __float2bfloat16(v);
        __nv_bfloat16 l = __float2bfloat16(v - __bfloat162float(h));
        size_t off = (size_t)z * 262144 + (size_t)(h0 + i) * 512 + d0 + tx;
        gWthi[off] = h;
        gWtlo[off] = l;
    }
}

// ---------------------------------------------------------------------------
// Kernel 3: QKV projection.  grid(1024, 4, 3)
// C[r, c] = A[r,:] . W[:,c], written to {Q,K,V}[n][t][c] with n=r%512, t=r/512
// ---------------------------------------------------------------------------
__global__ void __launch_bounds__(256, 1) k_proj() {
    __shared__ __align__(1024) char smem[2 * (2 * 128 * 32 + 2 * 128 * 32)];
    const size_t row0 = (size_t)blockIdx.x * 128;
    const int col0 = blockIdx.y * 128;
    const int w = blockIdx.z;

    const __nv_bfloat16* Ahi = gAhi + row0 * 512;
    const __nv_bfloat16* Alo = gAlo + row0 * 512;
    const __nv_bfloat16* Bhi = gWthi + ((size_t)w * 512 + col0) * 512;
    const __nv_bfloat16* Blo = gWtlo + ((size_t)w * 512 + col0) * 512;

    float acc[2][8][4];
    gemm_main<128, 128>(Ahi, Alo, 512, Bhi, Blo, 512, 512, smem, acc);

    __nv_bfloat16* Dhi = (w == 0) ? gQhi : (w == 1) ? gKhi : gVhi;
    __nv_bfloat16* Dlo = (w == 0) ? gQlo : (w == 1) ? gKlo : gVlo;

    const int tid = threadIdx.x, wid = tid >> 5, lane = tid & 31;
    const int wr = wid / 2, wc = wid % 2, gid = lane >> 2, t4 = lane & 3;
#pragma unroll
    for (int mt = 0; mt < 2; mt++)
#pragma unroll
        for (int sub = 0; sub < 2; sub++) {
            int rin = wr * 32 + mt * 16 + sub * 8 + gid;
            size_t gr = row0 + rin;
            size_t orow = (gr % 512) * 256 + (gr / 512);  // n*T + t
#pragma unroll
            for (int nt = 0; nt < 8; nt++) {
                int col = col0 + wc * 64 + nt * 8 + t4 * 2;
                split_store_pair(Dhi, Dlo, orow * 512 + col,
                                 acc[mt][nt][sub * 2], acc[mt][nt][sub * 2 + 1]);
            }
        }
}

// ---------------------------------------------------------------------------
// Kernel 4: V transpose per node: [n][s][o] -> [n][o][s], hi and lo
// grid(16, 8, 512), block(32, 8)
// ---------------------------------------------------------------------------
__global__ void __launch_bounds__(256) k_vt() {
    __shared__ __nv_bfloat16 tile[32][33];
    const int o0 = blockIdx.x * 32, s0 = blockIdx.y * 32, n = blockIdx.z;
    const int tx = threadIdx.x, ty = threadIdx.y;
    for (int half = 0; half < 2; half++) {
        const __nv_bfloat16* src = (half ? gVlo : gVhi) + (size_t)n * cT * 512;
        __nv_bfloat16* dst = (half ? gVtlo : gVthi) + (size_t)n * 512 * cT;
        for (int i = ty; i < 32; i += 8)
            tile[i][tx] = src[(size_t)(s0 + i) * 512 + o0 + tx];
        __syncthreads();
        for (int i = ty; i < 32; i += 8)
            dst[(size_t)(o0 + i) * cT + s0 + tx] = tile[tx][i];
        __syncthreads();
    }
}

// ---------------------------------------------------------------------------
// Kernel 5: scores + fused softmax -> P hi/lo.  grid(4, 512)
// BM=64 (t rows), BN=256 (all s), K=512 (h).  Warps: WR=2, WC=4.
// ---------------------------------------------------------------------------
__global__ void __launch_bounds__(256, 1) k_scores(const int* __restrict__ mask) {
    __shared__ __align__(1024) char smem[2 * (2 * 64 * 32 + 2 * 256 * 32)];
    __shared__ float red[4][64];

    const int t0 = blockIdx.x * 64;
    const int n = blockIdx.y;

    const __nv_bfloat16* Ahi = gQhi + ((size_t)n * cT + t0) * 512;
    const __nv_bfloat16* Alo = gQlo + ((size_t)n * cT + t0) * 512;
    const __nv_bfloat16* Bhi = gKhi + (size_t)n * cT * 512;
    const __nv_bfloat16* Blo = gKlo + (size_t)n * cT * 512;

    float acc[2][8][4];
    gemm_main<64, 256>(Ahi, Alo, 512, Bhi, Blo, 512, 512, smem, acc);

    const int tid = threadIdx.x, wid = tid >> 5, lane = tid & 31;
    const int wr = wid / 4, wc = wid % 4, gid = lane >> 2, t4 = lane & 3;
    const float scale = 0.044194173824159220f;  // 1/sqrt(512)

    // scale + mask
#pragma unroll
    for (int mt = 0; mt < 2; mt++)
#pragma unroll
        for (int nt = 0; nt < 8; nt++)
#pragma unroll
            for (int j = 0; j < 4; j++) {
                int col = wc * 64 + nt * 8 + t4 * 2 + (j & 1);
                float v = acc[mt][nt][j] * scale;
                if (mask[col] == 0) v = -1e9f;
                acc[mt][nt][j] = v;
            }

    // --- row max ---
    float rmax[4] = {-3.0e38f, -3.0e38f, -3.0e38f, -3.0e38f};
#pragma unroll
    for (int mt = 0; mt < 2; mt++)
#pragma unroll
        for (int nt = 0; nt < 8; nt++)
#pragma unroll
            for (int j = 0; j < 4; j++) {
                int ri = mt * 2 + (j >> 1);
                rmax[ri] = fmaxf(rmax[ri], acc[mt][nt][j]);
            }
#pragma unroll
    for (int r = 0; r < 4; r++) {
        rmax[r] = fmaxf(rmax[r], __shfl_xor_sync(0xffffffffu, rmax[r], 1));
        rmax[r] = fmaxf(rmax[r], __shfl_xor_sync(0xffffffffu, rmax[r], 2));
    }
    if (t4 == 0) {
#pragma unroll
        for (int r = 0; r < 4; r++) {
            int row = wr * 32 + (r >> 1) * 16 + (r & 1) * 8 + gid;
            red[wc][row] = rmax[r];
        }
    }
    __syncthreads();
#pragma unroll
    for (int r = 0; r < 4; r++) {
        int row = wr * 32 + (r >> 1) * 16 + (r & 1) * 8 + gid;
        rmax[r] = fmaxf(fmaxf(red[0][row], red[1][row]),
                        fmaxf(red[2][row], red[3][row]));
    }
    __syncthreads();  // before red reuse

    // --- exp + row sum ---
    float rsum[4] = {0.f, 0.f, 0.f, 0.f};
#pragma unroll
    for (int mt = 0; mt < 2; mt++)
#pragma unroll
        for (int nt = 0; nt < 8; nt++)
#pragma unroll
            for (int j = 0; j < 4; j++) {
                int ri = mt * 2 + (j >> 1);
                float e = __expf(acc[mt][nt][j] - rmax[ri]);
                acc[mt][nt][j] = e;
                rsum[ri] += e;
            }
#pragma unroll
    for (int r = 0; r < 4; r++) {
        rsum[r] += __shfl_xor_sync(0xffffffffu, rsum[r], 1);
        rsum[r] += __shfl_xor_sync(0xffffffffu, rsum[r], 2);
    }
    if (t4 == 0) {
#pragma unroll
        for (int r = 0; r < 4; r++) {
            int row = wr * 32 + (r >> 1) * 16 + (r & 1) * 8 + gid;
            red[wc][row] = rsum[r];
        }
    }
    __syncthreads();
    float rinv[4];
#pragma unroll
    for (int r = 0; r < 4; r++) {
        int row = wr * 32 + (r >> 1) * 16 + (r & 1) * 8 + gid;
        rinv[r] = 1.f / (red[0][row] + red[1][row] + red[2][row] + red[3][row]);
    }

    // --- store P hi/lo ---
#pragma unroll
    for (int mt = 0; mt < 2; mt++)
#pragma unroll
        for (int sub = 0; sub < 2; sub++) {
            int row = wr * 32 + mt * 16 + sub * 8 + gid;
            int ri = mt * 2 + sub;
            size_t base = ((size_t)n * cT + t0 + row) * cT;
#pragma unroll
            for (int nt = 0; nt < 8; nt++) {
                int col = wc * 64 + nt * 8 + t4 * 2;
                split_store_pair(gPhi, gPlo, base + col,
                                 acc[mt][nt][sub * 2] * rinv[ri],
                                 acc[mt][nt][sub * 2 + 1] * rinv[ri]);
            }
        }
}

// ---------------------------------------------------------------------------
// Kernel 6: out = P @ V (per node).  grid(2, 4, 512)
// A = P[n][t][s] (k=s), B = Vt[n][o][s] (k=s).  fp32 epilogue to d_out.
// ---------------------------------------------------------------------------
__global__ void __launch_bounds__(256, 1) k_pv(float* __restrict__ out) {
    __shared__ __align__(1024) char smem[2 * (2 * 128 * 32 + 2 * 128 * 32)];
    const int t0 = blockIdx.x * 128;
    const int o0 = blockIdx.y * 128;
    const int n = blockIdx.z;

    const __nv_bfloat16* Ahi = gPhi + ((size_t)n * cT + t0) * cT;
    const __nv_bfloat16* Alo = gPlo + ((size_t)n * cT + t0) * cT;
    const __nv_bfloat16* Bhi = gVthi + ((size_t)n * 512 + o0) * cT;
    const __nv_bfloat16* Blo = gVtlo + ((size_t)n * 512 + o0) * cT;

    float acc[2][8][4];
    gemm_main<128, 128>(Ahi, Alo, cT, Bhi, Blo, cT, cT, smem, acc);

    const int tid = threadIdx.x, wid = tid >> 5, lane = tid & 31;
    const int wr = wid / 2, wc = wid % 2, gid = lane >> 2, t4 = lane & 3;
#pragma unroll
    for (int mt = 0; mt < 2; mt++)
#pragma unroll
        for (int sub = 0; sub < 2; sub++) {
            int row = t0 + wr * 32 + mt * 16 + sub * 8 + gid;
            size_t base = ((size_t)row * 512 + n) * 512;
#pragma unroll
            for (int nt = 0; nt < 8; nt++) {
                int col = o0 + wc * 64 + nt * 8 + t4 * 2;
                float2 v = make_float2(acc[mt][nt][sub * 2],
                                       acc[mt][nt][sub * 2 + 1]);
                *reinterpret_cast<float2*>(out + base + col) = v;
            }
        }
}

// ---------------------------------------------------------------------------
// Launch
// ---------------------------------------------------------------------------
extern "C" void kernel_launch(void* const* d_in, const int* in_sizes, int n_in,
                              void* d_out, int out_size) {
    const float* inputs = (const float*)d_in[0];
    const float* Wq = (const float*)d_in[1];
    const float* Wk = (const float*)d_in[2];
    const float* Wv = (const float*)d_in[3];
    const int* mask = (const int*)d_in[4];
    float* out = (float*)d_out;

    k_split_in<<<65536, 256>>>(inputs);
    k_split_w<<<dim3(16, 16, 3), dim3(32, 8)>>>(Wq, Wk, Wv);
    k_proj<<<dim3(1024, 4, 3), 256>>>();
    k_vt<<<dim3(16, 8, 512), dim3(32, 8)>>>();
    k_scores<<<dim3(4, 512), 256>>>(mask);
    k_pv<<<dim3(2, 4, 512), 256>>>(out);
}

// round 5
// speedup vs baseline: 1.0099x; 1.0099x over previous
#include <cuda_runtime.h>
#include <cuda_bf16.h>
#include <cstdint>
#include <cstddef>
#include <math.h>

#define DEVI static __device__ __forceinline__

// Problem dims
constexpr int cT = 256, cN = 512, cD = 512, cH = 512, cO = 512;
constexpr size_t TN = (size_t)cT * cN;                    // 131072 rows
constexpr size_t QKV_E = (size_t)cN * cT * cH;            // 67108864 elems
constexpr size_t P_E = (size_t)cN * cT * cT;              // 33554432 elems

// ---------------------------------------------------------------------------
// Device-global scratch (allocation-free rule)
// ---------------------------------------------------------------------------
__device__ __nv_bfloat16 gAhi[TN * cD];
__device__ __nv_bfloat16 gAlo[TN * cD];
__device__ __nv_bfloat16 gWthi[3 * 512 * 512];
__device__ __nv_bfloat16 gWtlo[3 * 512 * 512];
__device__ __nv_bfloat16 gQhi[QKV_E], gQlo[QKV_E];   // [n][t][h]
__device__ __nv_bfloat16 gKhi[QKV_E], gKlo[QKV_E];   // [n][s][h]
__device__ __nv_bfloat16 gVhi[QKV_E], gVlo[QKV_E];   // [n][s][o]
__device__ __nv_bfloat16 gVthi[QKV_E], gVtlo[QKV_E]; // [n][o][s]
__device__ __nv_bfloat16 gPhi[P_E], gPlo[P_E];       // [n][t][s]

// ---------------------------------------------------------------------------
// Small helpers
// ---------------------------------------------------------------------------
DEVI uint32_t smem_u32(const void* p) {
    uint32_t a;
    asm("{ .reg .u64 t; cvta.to.shared.u64 t, %1; cvt.u32.u64 %0, t; }"
        : "=r"(a) : "l"(p));
    return a;
}
DEVI void cp16(uint32_t dst, const void* src) {
    asm volatile("cp.async.cg.shared.global [%0], [%1], 16;"
                 :: "r"(dst), "l"(src) : "memory");
}
DEVI void cp_commit() { asm volatile("cp.async.commit_group;" ::: "memory"); }
DEVI void cp_wait1()  { asm volatile("cp.async.wait_group 1;" ::: "memory"); }
DEVI uint32_t lds32(uint32_t a) {
    uint32_t v;
    asm volatile("ld.shared.b32 %0, [%1];" : "=r"(v) : "r"(a));
    return v;
}
DEVI void mma16816(float* c, const uint32_t* a, const uint32_t* b) {
    asm volatile(
        "mma.sync.aligned.m16n8k16.row.col.f32.bf16.bf16.f32 "
        "{%0,%1,%2,%3}, {%4,%5,%6,%7}, {%8,%9}, {%0,%1,%2,%3};"
        : "+f"(c[0]), "+f"(c[1]), "+f"(c[2]), "+f"(c[3])
        : "r"(a[0]), "r"(a[1]), "r"(a[2]), "r"(a[3]), "r"(b[0]), "r"(b[1]));
}
DEVI uint32_t pack2(__nv_bfloat16 a, __nv_bfloat16 b) {
    return (uint32_t)__bfloat16_as_ushort(a) |
           ((uint32_t)__bfloat16_as_ushort(b) << 16);
}
// split fp32 pair -> bf16 hi pair + bf16 lo pair, store as 32-bit each
DEVI void split_store_pair(__nv_bfloat16* hi, __nv_bfloat16* lo, size_t off,
                           float v0, float v1) {
    __nv_bfloat16 h0 = __float2bfloat16(v0);
    __nv_bfloat16 h1 = __float2bfloat16(v1);
    __nv_bfloat16 l0 = __float2bfloat16(v0 - __bfloat162float(h0));
    __nv_bfloat16 l1 = __float2bfloat16(v1 - __bfloat162float(h1));
    *reinterpret_cast<uint32_t*>(hi + off) = pack2(h0, h1);
    *reinterpret_cast<uint32_t*>(lo + off) = pack2(l0, l1);
}

// ---------------------------------------------------------------------------
// Shared GEMM core.
// A tiles: [BM rows][16 k] bf16, k-contiguous, 32B/row.  hi region then lo.
// B tiles: [BN rows(n)][16 k] bf16, k-contiguous.        hi region then lo.
// Per-warp tile fixed 32(M) x 64(N): MT=2 m16-tiles, NT=8 n8-tiles.
// Split-3: acc += Ahi*Bhi + Ahi*Blo + Alo*Bhi  (fp32)
// ---------------------------------------------------------------------------
template <int BM, int BN>
DEVI void gemm_main(const __nv_bfloat16* Ahi, const __nv_bfloat16* Alo, size_t lda,
                    const __nv_bfloat16* Bhi, const __nv_bfloat16* Blo, size_t ldb,
                    int K, char* smemRaw, float acc[2][8][4]) {
    constexpr int WC = BN / 64;                 // warp cols
    constexpr uint32_t AB = (uint32_t)BM * 32;  // bytes per A half-region
    constexpr uint32_t BB = (uint32_t)BN * 32;
    constexpr uint32_t STAGE = 2 * AB + 2 * BB;

    const uint32_t sb = smem_u32(smemRaw);
    const int tid = threadIdx.x;
    const int wid = tid >> 5, lane = tid & 31;
    const int wr = wid / WC, wc = wid % WC;
    const int gid = lane >> 2, t4 = lane & 3;

#pragma unroll
    for (int mt = 0; mt < 2; mt++)
#pragma unroll
        for (int nt = 0; nt < 8; nt++)
#pragma unroll
            for (int j = 0; j < 4; j++) acc[mt][nt][j] = 0.f;

    auto load_stage = [&](int k0, uint32_t base) {
        // A region (hi rows then lo rows), 2 x 16B chunks per row
        {
            const int total = BM * 4;
            for (int i = tid; i < total; i += 256) {
                int half = (i >= BM * 2);
                int j = half ? i - BM * 2 : i;
                int r = j >> 1, c = j & 1;
                const __nv_bfloat16* s =
                    (half ? Alo : Ahi) + (size_t)r * lda + k0 + c * 8;
                cp16(base + (half ? AB : 0u) + (uint32_t)(r * 32 + c * 16), s);
            }
        }
        // B region
        {
            const int total = BN * 4;
            for (int i = tid; i < total; i += 256) {
                int half = (i >= BN * 2);
                int j = half ? i - BN * 2 : i;
                int r = j >> 1, c = j & 1;
                const __nv_bfloat16* s =
                    (half ? Blo : Bhi) + (size_t)r * ldb + k0 + c * 8;
                cp16(base + 2 * AB + (half ? BB : 0u) +
                         (uint32_t)(r * 32 + c * 16), s);
            }
        }
        cp_commit();
    };

    const int NK = K / 16;
    load_stage(0, sb);
    for (int kt = 0; kt < NK; kt++) {
        const int cur = kt & 1;
        if (kt + 1 < NK) load_stage((kt + 1) * 16, sb + (uint32_t)(cur ^ 1) * STAGE);
        else cp_commit();  // empty group keeps the count consistent
        cp_wait1();
        __syncthreads();

        const uint32_t aBase = sb + (uint32_t)cur * STAGE;
        const uint32_t bBase = aBase + 2 * AB;

        uint32_t aH[2][4], aL[2][4], bH[8][2], bL[8][2];
#pragma unroll
        for (int mt = 0; mt < 2; mt++) {
            uint32_t r0 = aBase + (uint32_t)((wr * 32 + mt * 16 + gid) * 32 + t4 * 4);
            uint32_t r1 = r0 + 8 * 32;
            aH[mt][0] = lds32(r0);       aH[mt][1] = lds32(r1);
            aH[mt][2] = lds32(r0 + 16);  aH[mt][3] = lds32(r1 + 16);
            aL[mt][0] = lds32(r0 + AB);      aL[mt][1] = lds32(r1 + AB);
            aL[mt][2] = lds32(r0 + AB + 16); aL[mt][3] = lds32(r1 + AB + 16);
        }
#pragma unroll
        for (int nt = 0; nt < 8; nt++) {
            uint32_t r = bBase + (uint32_t)((wc * 64 + nt * 8 + gid) * 32 + t4 * 4);
            bH[nt][0] = lds32(r);       bH[nt][1] = lds32(r + 16);
            bL[nt][0] = lds32(r + BB);  bL[nt][1] = lds32(r + BB + 16);
        }
#pragma unroll
        for (int mt = 0; mt < 2; mt++)
#pragma unroll
            for (int nt = 0; nt < 8; nt++) {
                mma16816(acc[mt][nt], aH[mt], bH[nt]);
                mma16816(acc[mt][nt], aH[mt], bL[nt]);
                mma16816(acc[mt][nt], aL[mt], bH[nt]);
            }
        __syncthreads();
    }
}

// ---------------------------------------------------------------------------
// Kernel 1: split inputs fp32 -> bf16 hi/lo
// ---------------------------------------------------------------------------
__global__ void __launch_bounds__(256) k_split_in(const float* __restrict__ in) {
    size_t i = (size_t)blockIdx.x * 256 + threadIdx.x;  // one float4 each
    const float4 v = reinterpret_cast<const float4*>(in)[i];
    __nv_bfloat16 h0 = __float2bfloat16(v.x), h1 = __float2bfloat16(v.y);
    __nv_bfloat16 h2 = __float2bfloat16(v.z), h3 = __float2bfloat16(v.w);
    __nv_bfloat16 l0 = __float2bfloat16(v.x - __bfloat162float(h0));
    __nv_bfloat16 l1 = __float2bfloat16(v.y - __bfloat162float(h1));
    __nv_bfloat16 l2 = __float2bfloat16(v.z - __bfloat162float(h2));
    __nv_bfloat16 l3 = __float2bfloat16(v.w - __bfloat162float(h3));
    uint2 ph = make_uint2(pack2(h0, h1), pack2(h2, h3));
    uint2 pl = make_uint2(pack2(l0, l1), pack2(l2, l3));
    reinterpret_cast<uint2*>(gAhi)[i] = ph;
    reinterpret_cast<uint2*>(gAlo)[i] = pl;
}

// ---------------------------------------------------------------------------
// Kernel 2: transpose + split weights: Wt[w][h][d] = W[w][d][h]
// ---------------------------------------------------------------------------
__global__ void __launch_bounds__(256) k_split_w(const float* __restrict__ Wq,
                                                 const float* __restrict__ Wk,
                                                 const float* __restrict__ Wv) {
    __shared__ float tile[32][33];
    const int z = blockIdx.z;
    const float* W = (z == 0) ? Wq : (z == 1) ? Wk : Wv;
    const int d0 = blockIdx.x * 32, h0 = blockIdx.y * 32;
    const int tx = threadIdx.x, ty = threadIdx.y;  // block (32, 8)
    for (int i = ty; i < 32; i += 8)
        tile[i][tx] = W[(size_t)(d0 + i) * 512 + h0 + tx];
    __syncthreads();
    for (int i = ty; i < 32; i += 8) {
        float v = tile[tx][i];
        __nv_bfloat16 h = __float2bfloat16(v);
        __nv_bfloat16 l = __float2bfloat16(v - __bfloat162float(h));
        size_t off = (size_t)z * 262144 + (size_t)(h0 + i) * 512 + d0 + tx;
        gWthi[off] = h;
        gWtlo[off] = l;
    }
}

// ---------------------------------------------------------------------------
// Kernel 3: QKV projection.  grid(1024, 4, 3)
// C[r, c] = A[r,:] . W[:,c], written to {Q,K,V}[n][t][c] with n=r%512, t=r/512
// ---------------------------------------------------------------------------
__global__ void __launch_bounds__(256, 1) k_proj() {
    __shared__ __align__(1024) char smem[2 * (2 * 128 * 32 + 2 * 128 * 32)];
    const size_t row0 = (size_t)blockIdx.x * 128;
    const int col0 = blockIdx.y * 128;
    const int w = blockIdx.z;

    const __nv_bfloat16* Ahi = gAhi + row0 * 512;
    const __nv_bfloat16* Alo = gAlo + row0 * 512;
    const __nv_bfloat16* Bhi = gWthi + ((size_t)w * 512 + col0) * 512;
    const __nv_bfloat16* Blo = gWtlo + ((size_t)w * 512 + col0) * 512;

    float acc[2][8][4];
    gemm_main<128, 128>(Ahi, Alo, 512, Bhi, Blo, 512, 512, smem, acc);

    __nv_bfloat16* Dhi = (w == 0) ? gQhi : (w == 1) ? gKhi : gVhi;
    __nv_bfloat16* Dlo = (w == 0) ? gQlo : (w == 1) ? gKlo : gVlo;

    const int tid = threadIdx.x, wid = tid >> 5, lane = tid & 31;
    const int wr = wid / 2, wc = wid % 2, gid = lane >> 2, t4 = lane & 3;
#pragma unroll
    for (int mt = 0; mt < 2; mt++)
#pragma unroll
        for (int sub = 0; sub < 2; sub++) {
            int rin = wr * 32 + mt * 16 + sub * 8 + gid;
            size_t gr = row0 + rin;
            size_t orow = (gr % 512) * 256 + (gr / 512);  // n*T + t
#pragma unroll
            for (int nt = 0; nt < 8; nt++) {
                int col = col0 + wc * 64 + nt * 8 + t4 * 2;
                split_store_pair(Dhi, Dlo, orow * 512 + col,
                                 acc[mt][nt][sub * 2], acc[mt][nt][sub * 2 + 1]);
            }
        }
}

// ---------------------------------------------------------------------------
// Kernel 4: V transpose per node: [n][s][o] -> [n][o][s], hi and lo
// grid(16, 8, 512), block(32, 8)
// ---------------------------------------------------------------------------
__global__ void __launch_bounds__(256) k_vt() {
    __shared__ __nv_bfloat16 tile[32][33];
    const int o0 = blockIdx.x * 32, s0 = blockIdx.y * 32, n = blockIdx.z;
    const int tx = threadIdx.x, ty = threadIdx.y;
    for (int half = 0; half < 2; half++) {
        const __nv_bfloat16* src = (half ? gVlo : gVhi) + (size_t)n * cT * 512;
        __nv_bfloat16* dst = (half ? gVtlo : gVthi) + (size_t)n * 512 * cT;
        for (int i = ty; i < 32; i += 8)
            tile[i][tx] = src[(size_t)(s0 + i) * 512 + o0 + tx];
        __syncthreads();
        for (int i = ty; i < 32; i += 8)
            dst[(size_t)(o0 + i) * cT + s0 + tx] = tile[tx][i];
        __syncthreads();
    }
}

// ---------------------------------------------------------------------------
// Kernel 5: scores + fused softmax -> P hi/lo.  grid(4, 512)
// BM=64 (t rows), BN=256 (all s), K=512 (h).  Warps: WR=2, WC=4.
// ---------------------------------------------------------------------------
__global__ void __launch_bounds__(256, 1) k_scores(const int* __restrict__ mask) {
    __shared__ __align__(1024) char smem[2 * (2 * 64 * 32 + 2 * 256 * 32)];
    __shared__ float red[4][64];

    const int t0 = blockIdx.x * 64;
    const int n = blockIdx.y;

    const __nv_bfloat16* Ahi = gQhi + ((size_t)n * cT + t0) * 512;
    const __nv_bfloat16* Alo = gQlo + ((size_t)n * cT + t0) * 512;
    const __nv_bfloat16* Bhi = gKhi + (size_t)n * cT * 512;
    const __nv_bfloat16* Blo = gKlo + (size_t)n * cT * 512;

    float acc[2][8][4];
    gemm_main<64, 256>(Ahi, Alo, 512, Bhi, Blo, 512, 512, smem, acc);

    const int tid = threadIdx.x, wid = tid >> 5, lane = tid & 31;
    const int wr = wid / 4, wc = wid % 4, gid = lane >> 2, t4 = lane & 3;
    const float scale = 0.044194173824159220f;  // 1/sqrt(512)

    // scale + mask
#pragma unroll
    for (int mt = 0; mt < 2; mt++)
#pragma unroll
        for (int nt = 0; nt < 8; nt++)
#pragma unroll
            for (int j = 0; j < 4; j++) {
                int col = wc * 64 + nt * 8 + t4 * 2 + (j & 1);
                float v = acc[mt][nt][j] * scale;
                if (mask[col] == 0) v = -1e9f;
                acc[mt][nt][j] = v;
            }

    // --- row max ---
    float rmax[4] = {-3.0e38f, -3.0e38f, -3.0e38f, -3.0e38f};
#pragma unroll
    for (int mt = 0; mt < 2; mt++)
#pragma unroll
        for (int nt = 0; nt < 8; nt++)
#pragma unroll
            for (int j = 0; j < 4; j++) {
                int ri = mt * 2 + (j >> 1);
                rmax[ri] = fmaxf(rmax[ri], acc[mt][nt][j]);
            }
#pragma unroll
    for (int r = 0; r < 4; r++) {
        rmax[r] = fmaxf(rmax[r], __shfl_xor_sync(0xffffffffu, rmax[r], 1));
        rmax[r] = fmaxf(rmax[r], __shfl_xor_sync(0xffffffffu, rmax[r], 2));
    }
    if (t4 == 0) {
#pragma unroll
        for (int r = 0; r < 4; r++) {
            int row = wr * 32 + (r >> 1) * 16 + (r & 1) * 8 + gid;
            red[wc][row] = rmax[r];
        }
    }
    __syncthreads();
#pragma unroll
    for (int r = 0; r < 4; r++) {
        int row = wr * 32 + (r >> 1) * 16 + (r & 1) * 8 + gid;
        rmax[r] = fmaxf(fmaxf(red[0][row], red[1][row]),
                        fmaxf(red[2][row], red[3][row]));
    }
    __syncthreads();  // before red reuse

    // --- exp + row sum ---
    float rsum[4] = {0.f, 0.f, 0.f, 0.f};
#pragma unroll
    for (int mt = 0; mt < 2; mt++)
#pragma unroll
        for (int nt = 0; nt < 8; nt++)
#pragma unroll
            for (int j = 0; j < 4; j++) {
                int ri = mt * 2 + (j >> 1);
                float e = __expf(acc[mt][nt][j] - rmax[ri]);
                acc[mt][nt][j] = e;
                rsum[ri] += e;
            }
#pragma unroll
    for (int r = 0; r < 4; r++) {
        rsum[r] += __shfl_xor_sync(0xffffffffu, rsum[r], 1);
        rsum[r] += __shfl_xor_sync(0xffffffffu, rsum[r], 2);
    }
    if (t4 == 0) {
#pragma unroll
        for (int r = 0; r < 4; r++) {
            int row = wr * 32 + (r >> 1) * 16 + (r & 1) * 8 + gid;
            red[wc][row] = rsum[r];
        }
    }
    __syncthreads();
    float rinv[4];
#pragma unroll
    for (int r = 0; r < 4; r++) {
        int row = wr * 32 + (r >> 1) * 16 + (r & 1) * 8 + gid;
        rinv[r] = 1.f / (red[0][row] + red[1][row] + red[2][row] + red[3][row]);
    }

    // --- store P hi/lo ---
#pragma unroll
    for (int mt = 0; mt < 2; mt++)
#pragma unroll
        for (int sub = 0; sub < 2; sub++) {
            int row = wr * 32 + mt * 16 + sub * 8 + gid;
            int ri = mt * 2 + sub;
            size_t base = ((size_t)n * cT + t0 + row) * cT;
#pragma unroll
            for (int nt = 0; nt < 8; nt++) {
                int col = wc * 64 + nt * 8 + t4 * 2;
                split_store_pair(gPhi, gPlo, base + col,
                                 acc[mt][nt][sub * 2] * rinv[ri],
                                 acc[mt][nt][sub * 2 + 1] * rinv[ri]);
            }
        }
}

// ---------------------------------------------------------------------------
// Kernel 6: out = P @ V (per node).  grid(2, 4, 512)
// A = P[n][t][s] (k=s), B = Vt[n][o][s] (k=s).  fp32 epilogue to d_out.
// ---------------------------------------------------------------------------
__global__ void __launch_bounds__(256, 1) k_pv(float* __restrict__ out) {
    __shared__ __align__(1024) char smem[2 * (2 * 128 * 32 + 2 * 128 * 32)];
    const int t0 = blockIdx.x * 128;
    const int o0 = blockIdx.y * 128;
    const int n = blockIdx.z;

    const __nv_bfloat16* Ahi = gPhi + ((size_t)n * cT + t0) * cT;
    const __nv_bfloat16* Alo = gPlo + ((size_t)n * cT + t0) * cT;
    const __nv_bfloat16* Bhi = gVthi + ((size_t)n * 512 + o0) * cT;
    const __nv_bfloat16* Blo = gVtlo + ((size_t)n * 512 + o0) * cT;

    float acc[2][8][4];
    gemm_main<128, 128>(Ahi, Alo, cT, Bhi, Blo, cT, cT, smem, acc);

    const int tid = threadIdx.x, wid = tid >> 5, lane = tid & 31;
    const int wr = wid / 2, wc = wid % 2, gid = lane >> 2, t4 = lane & 3;
#pragma unroll
    for (int mt = 0; mt < 2; mt++)
#pragma unroll
        for (int sub = 0; sub < 2; sub++) {
            int row = t0 + wr * 32 + mt * 16 + sub * 8 + gid;
            size_t base = ((size_t)row * 512 + n) * 512;
#pragma unroll
            for (int nt = 0; nt < 8; nt++) {
                int col = o0 + wc * 64 + nt * 8 + t4 * 2;
                float2 v = make_float2(acc[mt][nt][sub * 2],
                                       acc[mt][nt][sub * 2 + 1]);
                *reinterpret_cast<float2*>(out + base + col) = v;
            }
        }
}

// ---------------------------------------------------------------------------
// Launch
// ---------------------------------------------------------------------------
extern "C" void kernel_launch(void* const* d_in, const int* in_sizes, int n_in,
                              void* d_out, int out_size) {
    const float* inputs = (const float*)d_in[0];
    const float* Wq = (const float*)d_in[1];
    const float* Wk = (const float*)d_in[2];
    const float* Wv = (const float*)d_in[3];
    const int* mask = (const int*)d_in[4];
    float* out = (float*)d_out;

    k_split_in<<<65536, 256>>>(inputs);
    k_split_w<<<dim3(16, 16, 3), dim3(32, 8)>>>(Wq, Wk, Wv);
    k_proj<<<dim3(1024, 4, 3), 256>>>();
    k_vt<<<dim3(16, 8, 512), dim3(32, 8)>>>();
    k_scores<<<dim3(4, 512), 256>>>(mask);
    k_pv<<<dim3(2, 4, 512), 256>>>(out);
}